// round 16
// baseline (speedup 1.0000x reference)
#include <cuda_runtime.h>
#include <cuda_bf16.h>
#include <cstdint>

// FINAL KERNEL — v8 (256-bit) memory-op variant, best of 6 measured variants.
//
// World-model (established by rel_err forensics, confirmed rel_err = 0.0):
//   d_in[0] = res  : float32 [M, N, D]  (harness serializes bf16 -> f32, exact)
//   d_in[1] = h_pre: float32 [M, N]
//   d_out   = out  : float32 [M, D]
// out[m,d] = f32( bf16_round( sum_n res[m,n,d] * h[m,n] ) ), fp32 accum.
//
// Measured plateau: 182.6-183.9us (ncu) across 5 structural variants, all at
// 90-91% of HBM spec (7.2-7.26 TB/s) — the streaming roofline. v8 ops halved
// L1tex wavefronts (L1 43%->23%) and are the best measured (186.1us bench).
// Rejected by measurement: streaming cache hints (neutral), persistent CTAs
// (+43%), 2 rows/CTA (+4%), 256-thr half-row CTAs (neutral).
static constexpr int M_DIM = 16384;
static constexpr int N_DIM = 4;
static constexpr int D_DIM = 4096;
static constexpr long long RES_ELEMS = (long long)M_DIM * N_DIM * D_DIM;

struct alignas(32) f32x8 { float v[8]; };

__device__ __forceinline__ f32x8 ldg_v8(const float* p) {
    f32x8 r;
    asm volatile("ld.global.v8.f32 {%0,%1,%2,%3,%4,%5,%6,%7}, [%8];"
                 : "=f"(r.v[0]), "=f"(r.v[1]), "=f"(r.v[2]), "=f"(r.v[3]),
                   "=f"(r.v[4]), "=f"(r.v[5]), "=f"(r.v[6]), "=f"(r.v[7])
                 : "l"(p));
    return r;
}

__device__ __forceinline__ void stg_v8(float* p, const f32x8& r) {
    asm volatile("st.global.v8.f32 [%0], {%1,%2,%3,%4,%5,%6,%7,%8};"
                 :: "l"(p),
                    "f"(r.v[0]), "f"(r.v[1]), "f"(r.v[2]), "f"(r.v[3]),
                    "f"(r.v[4]), "f"(r.v[5]), "f"(r.v[6]), "f"(r.v[7])
                 : "memory");
}

// One CTA per row m, 512 threads, 8 consecutive f32 (32 B) per thread.
// 4 independent 256-bit loads (issued FIRST — L1tex queue head), then the
// L1-hit weight load, 32 FMA, bf16 round, 1 256-bit store.
__global__ void __launch_bounds__(512, 2)
mhc_wsum_v8_kernel(const float* __restrict__ res,
                   const float* __restrict__ h_pre,
                   float* __restrict__ out)
{
    const int m = blockIdx.x;
    const int t = threadIdx.x;              // 0..511
    const int d0 = t * 8;                   // 32-byte aligned

    const float* base = res + (size_t)m * N_DIM * D_DIM + d0;

    // Long-latency streaming loads first: 4 independent 256-bit requests.
    f32x8 v[N_DIM];
#pragma unroll
    for (int n = 0; n < N_DIM; ++n) {
        v[n] = ldg_v8(base + (size_t)n * D_DIM);
    }

    // Per-row weights (16 B, L1-broadcast) — issued after the misses.
    const float4 w4 = *reinterpret_cast<const float4*>(h_pre + (size_t)m * N_DIM);
    const float w[4] = {w4.x, w4.y, w4.z, w4.w};

    float acc[8] = {0,0,0,0,0,0,0,0};
#pragma unroll
    for (int n = 0; n < N_DIM; ++n) {
        const float wn = w[n];
#pragma unroll
        for (int j = 0; j < 8; ++j) {
            acc[j] = fmaf(v[n].v[j], wn, acc[j]);
        }
    }

    // Round through bf16 (matches reference .astype(bfloat16)), widen to f32.
    f32x8 r;
#pragma unroll
    for (int j = 0; j < 8; ++j) {
        r.v[j] = __bfloat162float(__float2bfloat16_rn(acc[j]));
    }

    stg_v8(out + (size_t)m * D_DIM + d0, r);
}

extern "C" void kernel_launch(void* const* d_in, const int* in_sizes, int n_in,
                              void* d_out, int out_size)
{
    const float* res;
    const float* h;
    if ((long long)in_sizes[0] == RES_ELEMS) {
        res = (const float*)d_in[0];
        h   = (const float*)d_in[1];
    } else {
        res = (const float*)d_in[1];
        h   = (const float*)d_in[0];
    }

    float* out = (float*)d_out;
    mhc_wsum_v8_kernel<<<M_DIM, 512>>>(res, h, out);
}